// round 16
// baseline (speedup 1.0000x reference)
#include <cuda_runtime.h>
#include <cuda_fp16.h>
#include <math.h>

#define DIM 2048
#define NH  16
#define HD  128
#define B2  2
#define T2  2048
#define BT  4096   // B*T
#define BH  32     // B*NH

// ---------------- device scratch ----------------
__device__ __half g_Wq[DIM*DIM];
__device__ __half g_Wk[DIM*DIM];
__device__ __half g_Wv[DIM*DIM];
__device__ __half g_Wo[DIM*DIM];
__device__ __half g_Xh[BT*DIM];      // x in fp16
__device__ __half g_Qh[BH*T2*HD];    // post-RoPE fp16 (scale folded)
__device__ __half g_Kh[BH*T2*HD];
__device__ __half g_Vt[BH*HD*T2];    // V transposed fp16 [BH][HD][T]
__device__ __half g_Y2[BT*DIM];      // attention out fp16 [BT][DIM]

// ---------------- helpers ----------------
__device__ __forceinline__ void mma16(float* d, const unsigned* a, const unsigned* b){
    asm volatile("mma.sync.aligned.m16n8k16.row.col.f32.f16.f16.f32 "
                 "{%0,%1,%2,%3},{%4,%5,%6,%7},{%8,%9},{%0,%1,%2,%3};"
                 : "+f"(d[0]),"+f"(d[1]),"+f"(d[2]),"+f"(d[3])
                 : "r"(a[0]),"r"(a[1]),"r"(a[2]),"r"(a[3]),"r"(b[0]),"r"(b[1]));
}
__device__ __forceinline__ void ldsm4(unsigned* r, unsigned addr){
    asm volatile("ldmatrix.sync.aligned.m8n8.x4.shared.b16 {%0,%1,%2,%3}, [%4];"
                 : "=r"(r[0]),"=r"(r[1]),"=r"(r[2]),"=r"(r[3]) : "r"(addr));
}
__device__ __forceinline__ unsigned packh2(float a, float b){
    __half2 h = __floats2half2_rn(a, b);
    return *(unsigned*)&h;
}

// ---------------- ternary dequant -> fp16 (all 4 weights, one launch) --------
__global__ void __launch_bounds__(256) dequant4_kernel(
    const float* __restrict__ w0, const float* __restrict__ w1,
    const float* __restrict__ w2, const float* __restrict__ w3,
    __half* __restrict__ o0, __half* __restrict__ o1,
    __half* __restrict__ o2, __half* __restrict__ o3)
{
    const float* w; __half* o;
    switch (blockIdx.y){
        case 0: w=w0; o=o0; break;
        case 1: w=w1; o=o1; break;
        case 2: w=w2; o=o2; break;
        default: w=w3; o=o3; break;
    }
    int row = blockIdx.x;
    int tid = threadIdx.x;
    const float* wr = w + (size_t)row*DIM + tid*8;
    float v[8]; float s = 0.f;
    #pragma unroll
    for (int i=0;i<8;i++){ v[i]=wr[i]; s += fabsf(v[i]); }
    #pragma unroll
    for (int off=8; off; off>>=1)
        s += __shfl_xor_sync(0xffffffffu, s, off, 16);
    float scale = fmaxf(s*(1.0f/128.0f), 1e-8f);
    float inv = 1.0f/scale;
    __half* orow = o + (size_t)row*DIM + tid*8;
    #pragma unroll
    for (int i=0;i<4;i++){
        float wn0 = v[2*i]*inv, wn1 = v[2*i+1]*inv;
        float q0 = (wn0 > 0.5f) ? 1.0f : ((wn0 < -0.5f) ? -1.0f : 0.0f);
        float q1 = (wn1 > 0.5f) ? 1.0f : ((wn1 < -0.5f) ? -1.0f : 0.0f);
        *(__half2*)(orow + 2*i) = __floats2half2_rn(q0*scale, q1*scale);
    }
}

// ---------------- f32 -> f16 convert ----------------
__global__ void __launch_bounds__(256) tohalf_kernel(
    const float* __restrict__ in, __half* __restrict__ out)
{
    size_t i = ((size_t)blockIdx.x*256 + threadIdx.x)*8;
    float4 a = *(const float4*)(in + i);
    float4 b = *(const float4*)(in + i + 4);
    __half2 h[4];
    h[0]=__floats2half2_rn(a.x,a.y); h[1]=__floats2half2_rn(a.z,a.w);
    h[2]=__floats2half2_rn(b.x,b.y); h[3]=__floats2half2_rn(b.z,b.w);
    *(uint4*)(out + i) = *(uint4*)h;
}

// ====== GEMM core: CTA 128x128, 128 threads (4 warps 2m x 2n), warp 64x64 ====
// BK=32, double-buffered smem, stride 40 halves (conflict-free ldmatrix).
#define AH 40
#define GH (128*AH)                 // halves per matrix per buffer
#define SF 132                      // fp32 staging stride (words)
#define SH 130                      // fp16 staging stride (halves)
#define GEMM_SMEM (128*SF*4)        // 67584 B (covers mainloop 40960 B too)

#define GEMM_MAINLOOP(A_, B_, K_) \
    int warp = tid>>5, lane = tid&31; \
    int wm   = (warp&1)<<6; \
    int wn   = (warp>>1)<<6; \
    int g    = lane>>2, t = lane&3; \
    int arow = ((lane>>3)&1)*8 + (lane&7); \
    int acol = (lane>>4)*8; \
    int brow = ((lane>>4)&1)*8 + (lane&7); \
    int bcol = ((lane>>3)&1)*8; \
    unsigned uA = (unsigned)__cvta_generic_to_shared(As); \
    unsigned uB = (unsigned)__cvta_generic_to_shared(Bs); \
    float acc[4][8][4]; \
    _Pragma("unroll") \
    for(int i=0;i<4;i++) \
        _Pragma("unroll") \
        for(int j=0;j<8;j++) \
            _Pragma("unroll") \
            for(int r=0;r<4;r++) acc[i][j][r]=0.f; \
    int lr = tid>>1; \
    int lc = (tid&1)<<4; \
    const __half* Ag = (A_) + (size_t)(bm*128 + lr)*(K_) + lc; \
    const __half* Bg = (B_) + (size_t)(bn*128 + lr)*(K_) + lc; \
    int soff[2][2]; \
    _Pragma("unroll") \
    for(int r=0;r<2;r++) \
        _Pragma("unroll") \
        for(int c=0;c<2;c++) \
            soff[r][c] = (lr + r*64)*AH + lc + c*8; \
    uint4 av[2][2], bv[2][2]; \
    _Pragma("unroll") \
    for(int r=0;r<2;r++) \
        _Pragma("unroll") \
        for(int c=0;c<2;c++){ \
            av[r][c] = *(const uint4*)(Ag + (size_t)r*64*(K_) + c*8); \
            bv[r][c] = *(const uint4*)(Bg + (size_t)r*64*(K_) + c*8); \
        } \
    _Pragma("unroll") \
    for(int r=0;r<2;r++) \
        _Pragma("unroll") \
        for(int c=0;c<2;c++){ \
            *(uint4*)&As[soff[r][c]] = av[r][c]; \
            *(uint4*)&Bs[soff[r][c]] = bv[r][c]; \
        } \
    int buf = 0; \
    for(int k0=0; k0<(K_); k0+=32){ \
        __syncthreads(); \
        bool more = (k0+32 < (K_)); \
        if (more){ \
            _Pragma("unroll") \
            for(int r=0;r<2;r++) \
                _Pragma("unroll") \
                for(int c=0;c<2;c++){ \
                    av[r][c] = *(const uint4*)(Ag + k0+32 + (size_t)r*64*(K_) + c*8); \
                    bv[r][c] = *(const uint4*)(Bg + k0+32 + (size_t)r*64*(K_) + c*8); \
                } \
        } \
        unsigned a_lane = uA + (buf*GH + (wm + arow)*AH + acol)*2; \
        unsigned b_lane = uB + (buf*GH + (wn + brow)*AH + bcol)*2; \
        _Pragma("unroll") \
        for(int ks=0;ks<2;ks++){ \
            unsigned af[4][4], bf[4][4]; \
            _Pragma("unroll") \
            for(int mi=0;mi<4;mi++) \
                ldsm4(af[mi], a_lane + (mi*16*AH + ks*16)*2); \
            _Pragma("unroll") \
            for(int p=0;p<4;p++) \
                ldsm4(bf[p], b_lane + (p*16*AH + ks*16)*2); \
            _Pragma("unroll") \
            for(int mi=0;mi<4;mi++) \
                _Pragma("unroll") \
                for(int ni=0;ni<8;ni++) \
                    mma16(acc[mi][ni], af[mi], &bf[ni>>1][(ni&1)*2]); \
        } \
        if (more){ \
            int nb = buf^1; \
            _Pragma("unroll") \
            for(int r=0;r<2;r++) \
                _Pragma("unroll") \
                for(int c=0;c<2;c++){ \
                    *(uint4*)&As[nb*GH + soff[r][c]] = av[r][c]; \
                    *(uint4*)&Bs[nb*GH + soff[r][c]] = bv[r][c]; \
                } \
        } \
        buf ^= 1; \
    }

// ---------------- fused QKV GEMM: blockIdx.z selects weight/output ----------
__global__ void __launch_bounds__(128,2) gemm_qkv_kernel(
    const __half* __restrict__ A,
    const __half* __restrict__ Bq, const __half* __restrict__ Bk,
    const __half* __restrict__ Bv,
    __half* __restrict__ Oq, __half* __restrict__ Ok, __half* __restrict__ Ov)
{
    extern __shared__ __align__(16) __half dsm[];
    __half* As = dsm;                 // 2 x [128][40]
    __half* Bs = dsm + 2*GH;          // 2 x [128][40]
    int tid = threadIdx.x;
    int bm  = blockIdx.y, bn = blockIdx.x;
    int z   = blockIdx.z;
    const __half* Bw = (z==0) ? Bq : (z==1) ? Bk : Bv;
    __half* Ch       = (z==0) ? Oq : (z==1) ? Ok : Ov;
    float scale      = (z==0) ? 0.08838834764831845f : 1.0f;

    GEMM_MAINLOOP(A, Bw, DIM)

    __syncthreads();

    int b_ = bm >> 4;
    int tb = (bm & 15) * 128;
    int h  = bn;

    if (z < 2){
        float* S = (float*)dsm;
        #pragma unroll
        for(int mi=0;mi<4;mi++){
            #pragma unroll
            for(int ni=0;ni<8;ni++){
                int row = wm + mi*16 + g;
                int col = wn + ni*8 + 2*t;
                *(float2*)&S[row*SF + col]     = make_float2(acc[mi][ni][0], acc[mi][ni][1]);
                *(float2*)&S[(row+8)*SF + col] = make_float2(acc[mi][ni][2], acc[mi][ni][3]);
            }
        }
        __syncthreads();
        __half* outp = Ch + ((size_t)(b_*NH + h)*T2 + tb)*HD;
        #pragma unroll
        for (int k=0;k<64;k++){
            int e = tid + k*128;       // 128 rows x 64 pairs
            int row = e >> 6, j = e & 63;
            float x1 = S[row*SF + j], x2 = S[row*SF + j + 64];
            float invf = exp2f(-(float)j * (13.287712379549449f/64.0f));
            float ang  = (float)(tb + row) * invf;
            float sn, cs; sincosf(ang, &sn, &cs);
            outp[(size_t)row*HD + j]      = __float2half_rn((x1*cs - x2*sn)*scale);
            outp[(size_t)row*HD + j + 64] = __float2half_rn((x1*sn + x2*cs)*scale);
        }
    } else {
        __half* S = dsm;
        #pragma unroll
        for(int mi=0;mi<4;mi++){
            #pragma unroll
            for(int ni=0;ni<8;ni++){
                int row = wm + mi*16 + g;
                int col = wn + ni*8 + 2*t;
                *(__half2*)&S[row*SH + col]     = __floats2half2_rn(acc[mi][ni][0], acc[mi][ni][1]);
                *(__half2*)&S[(row+8)*SH + col] = __floats2half2_rn(acc[mi][ni][2], acc[mi][ni][3]);
            }
        }
        __syncthreads();
        __half* outp = Ch + ((size_t)(b_*NH + h)*HD)*T2 + tb;
        #pragma unroll
        for (int k=0;k<128;k++){
            int e = tid + k*128;       // 128 d x 128 t
            int d = e >> 7, tt = e & 127;
            outp[(size_t)d*T2 + tt] = S[tt*SH + d];
        }
    }
}

// ---------------- output GEMM: fp32 row-major ----------------
__global__ void __launch_bounds__(128,2) gemm_out_kernel(
    const __half* __restrict__ A, const __half* __restrict__ Bw,
    float* __restrict__ Cf)
{
    extern __shared__ __align__(16) __half dsm[];
    __half* As = dsm;
    __half* Bs = dsm + 2*GH;
    int tid = threadIdx.x;
    int bm  = blockIdx.y, bn = blockIdx.x;

    GEMM_MAINLOOP(A, Bw, DIM)

    #pragma unroll
    for(int mi=0;mi<4;mi++){
        #pragma unroll
        for(int ni=0;ni<8;ni++){
            int rowa = bm*128 + wm + mi*16 + g;
            int col  = bn*128 + wn + ni*8 + 2*t;
            *(float2*)(Cf + (size_t)rowa*DIM + col) =
                make_float2(acc[mi][ni][0], acc[mi][ni][1]);
            *(float2*)(Cf + (size_t)(rowa+8)*DIM + col) =
                make_float2(acc[mi][ni][2], acc[mi][ni][3]);
        }
    }
}

// ---------------- fp16 flash attention: BM=64, P in registers ----------------
#define QH 136
#define VH 72
#define FL_Q (64*QH)
#define FL_K (64*QH)
#define FL_V (128*VH)
#define FL_SMEM ((FL_Q + 2*FL_K + 2*FL_V)*2)   // 89088 bytes

__global__ void __launch_bounds__(128,2) flash3_kernel(
    const __half* __restrict__ Q, const __half* __restrict__ K,
    const __half* __restrict__ Vt, __half* __restrict__ Y2)
{
    extern __shared__ __align__(16) __half smh[];
    __half* Qs = smh;                // [64][136]
    __half* Ks = Qs + FL_Q;          // 2 x [64][136]
    __half* Vs = Ks + 2*FL_K;        // 2 x [128][72]

    int qb  = (int)(gridDim.x - 1 - blockIdx.x);
    int bh  = blockIdx.y;
    int tid = threadIdx.x;
    int warp = tid >> 5, lane = tid & 31;
    int g = lane >> 2, t = lane & 3;

    int arow = ((lane>>3)&1)*8 + (lane&7);
    int acol = (lane>>4)*8;
    int brow = ((lane>>4)&1)*8 + (lane&7);
    int bcol = ((lane>>3)&1)*8;
    unsigned uQ = (unsigned)__cvta_generic_to_shared(Qs);
    unsigned uK = (unsigned)__cvta_generic_to_shared(Ks);
    unsigned uV = (unsigned)__cvta_generic_to_shared(Vs);
    unsigned q_lane = uQ + ((warp*16 + arow)*QH + acol)*2;

    const __half* qg = Q  + ((size_t)bh*T2 + qb*64)*HD;
    const __half* kg = K  + (size_t)bh*T2*HD;
    const __half* vg = Vt + (size_t)bh*HD*T2;

    int kr = tid >> 4, kc = (tid & 15) << 3;
    int vd = tid >> 3, vc = (tid & 7) << 3;

    #pragma unroll
    for (int it=0; it<8; it++){
        int idx = tid + it*128;
        int r = idx >> 4, c = (idx & 15) << 3;
        *(uint4*)&Qs[r*QH + c] = *(const uint4*)(qg + (size_t)r*HD + c);
    }
    uint4 kvreg[16];
    #pragma unroll
    for (int it=0; it<8; it++)
        kvreg[it] = *(const uint4*)(kg + (size_t)(kr + it*8)*HD + kc);
    #pragma unroll
    for (int it=0; it<8; it++)
        kvreg[8+it] = *(const uint4*)(vg + (size_t)(vd + it*16)*T2 + vc);
    #pragma unroll
    for (int it=0; it<8; it++)
        *(uint4*)&Ks[(kr + it*8)*QH + kc] = kvreg[it];
    #pragma unroll
    for (int it=0; it<8; it++)
        *(uint4*)&Vs[(vd + it*16)*VH + vc] = kvreg[8+it];

    float l0 = 0.f, l1 = 0.f;
    float o[16][4];
    #pragma unroll
    for (int i=0;i<16;i++)
        #pragma unroll
        for (int r=0;r<4;r++) o[i][r]=0.f;

    int prow = warp*16 + g;
    int nkb = qb + 1;

    for (int kb=0; kb<nkb; kb++){
        int buf = kb & 1;
        __syncthreads();
        bool more = (kb+1 < nkb);
        if (more){
            #pragma unroll
            for (int it=0; it<8; it++)
                kvreg[it] = *(const uint4*)(kg + (size_t)((kb+1)*64 + kr + it*8)*HD + kc);
            #pragma unroll
            for (int it=0; it<8; it++)
                kvreg[8+it] = *(const uint4*)(vg + (size_t)(vd + it*16)*T2 + (kb+1)*64 + vc);
        }
        unsigned k_lane = uK + (buf*FL_K + brow*QH + bcol)*2;
        unsigned v_lane = uV + (buf*FL_V + brow*VH + bcol)*2;

        float s[8][4];
        #pragma unroll
        for (int ni=0;ni<8;ni++)
            #pragma unroll
            for (int r=0;r<4;r++) s[ni][r]=0.f;
        #pragma unroll
        for (int ks=0; ks<8; ks++){
            unsigned af[4], kf[4][4];
            ldsm4(af, q_lane + ks*32);
            #pragma unroll
            for (int p=0;p<4;p++)
                ldsm4(kf[p], k_lane + (p*16*QH + ks*16)*2);
            #pragma unroll
            for (int ni=0;ni<8;ni++)
                mma16(s[ni], af, &kf[ni>>1][(ni&1)*2]);
        }

        if (kb == qb){
            int q0 = qb*64 + prow, q1 = q0 + 8;
            #pragma unroll
            for (int ni=0;ni<8;ni++){
                int k0 = kb*64 + ni*8 + 2*t;
                if (k0   > q0) s[ni][0] = -1e30f;
                if (k0+1 > q0) s[ni][1] = -1e30f;
                if (k0   > q1) s[ni][2] = -1e30f;
                if (k0+1 > q1) s[ni][3] = -1e30f;
            }
        }

        #pragma unroll
        for (int ni=0;ni<8;ni++){
            s[ni][0] = __expf(s[ni][0]); l0 += s[ni][0];
            s[ni][1] = __expf(s[ni][1]); l0 += s[ni][1];
            s[ni][2] = __expf(s[ni][2]); l1 += s[ni][2];
            s[ni][3] = __expf(s[ni][3]); l1 += s[ni][3];
        }

        #pragma unroll
        for (int ks=0; ks<4; ks++){
            unsigned af[4], vf[8][4];
            af[0] = packh2(s[2*ks][0],   s[2*ks][1]);
            af[1] = packh2(s[2*ks][2],   s[2*ks][3]);
            af[2] = packh2(s[2*ks+1][0], s[2*ks+1][1]);
            af[3] = packh2(s[2*ks+1][2], s[2*ks+1][3]);
            #pragma unroll
            for (int p=0;p<8;p++)
                ldsm4(vf[p], v_lane + (p*16*VH + ks*16)*2);
            #pragma unroll
            for (int ti=0;ti<16;ti++)
                mma16(o[ti], af, &vf[ti>>1][(ti&1)*2]);
        }

        if (more){
            int nb = buf^1;
            #pragma unroll
            for (int it=0; it<8; it++)
                *(uint4*)&Ks[nb*FL_K + (kr + it*8)*QH + kc] = kvreg[it];
            #pragma unroll
            for (int it=0; it<8; it++)
                *(uint4*)&Vs[nb*FL_V + (vd + it*16)*VH + vc] = kvreg[8+it];
        }
    }

    #pragma unroll
    for (int off=1; off<4; off<<=1){
        l0 += __shfl_xor_sync(0xffffffffu, l0, off, 4);
        l1 += __shfl_xor_sync(0xffffffffu, l1, off, 4);
    }

    float i0 = 1.0f/l0, i1 = 1.0f/l1;
    int trow = qb*64 + prow;
    int b_ = bh >> 4, h = bh & 15;
    __half* yr = Y2 + ((size_t)b_*T2)*DIM + h*HD;
    #pragma unroll
    for (int ti=0;ti<16;ti++){
        int col = ti*8 + 2*t;
        *(__half2*)(yr + (size_t)trow*DIM + col) =
            __floats2half2_rn(o[ti][0]*i0, o[ti][1]*i0);
        *(__half2*)(yr + (size_t)(trow+8)*DIM + col) =
            __floats2half2_rn(o[ti][2]*i1, o[ti][3]*i1);
    }
}

// ---------------- launch ----------------
extern "C" void kernel_launch(void* const* d_in, const int* in_sizes, int n_in,
                              void* d_out, int out_size)
{
    const float* x  = (const float*)d_in[0];
    const float* wq = (const float*)d_in[1];
    const float* wk = (const float*)d_in[2];
    const float* wv = (const float*)d_in[3];
    const float* wo = (const float*)d_in[4];
    float* out = (float*)d_out;

    __half *Wq,*Wk,*Wv,*Wo,*Xh,*Qh,*Kh,*Vt,*Y2;
    cudaGetSymbolAddress((void**)&Wq, g_Wq);
    cudaGetSymbolAddress((void**)&Wk, g_Wk);
    cudaGetSymbolAddress((void**)&Wv, g_Wv);
    cudaGetSymbolAddress((void**)&Wo, g_Wo);
    cudaGetSymbolAddress((void**)&Xh, g_Xh);
    cudaGetSymbolAddress((void**)&Qh, g_Qh);
    cudaGetSymbolAddress((void**)&Kh, g_Kh);
    cudaGetSymbolAddress((void**)&Vt, g_Vt);
    cudaGetSymbolAddress((void**)&Y2, g_Y2);

    cudaFuncSetAttribute(gemm_qkv_kernel,
        cudaFuncAttributeMaxDynamicSharedMemorySize, GEMM_SMEM);
    cudaFuncSetAttribute(gemm_out_kernel,
        cudaFuncAttributeMaxDynamicSharedMemorySize, GEMM_SMEM);
    cudaFuncSetAttribute(flash3_kernel,
        cudaFuncAttributeMaxDynamicSharedMemorySize, FL_SMEM);

    dequant4_kernel<<<dim3(DIM,4),256>>>(wq, wk, wv, wo, Wq, Wk, Wv, Wo);
    tohalf_kernel<<<(BT*DIM)/2048, 256>>>(x, Xh);

    gemm_qkv_kernel<<<dim3(DIM/128, BT/128, 3),128,GEMM_SMEM>>>(
        Xh, Wq, Wk, Wv, Qh, Kh, Vt);

    flash3_kernel<<<dim3(T2/64, BH), 128, FL_SMEM>>>(Qh, Kh, Vt, Y2);

    gemm_out_kernel<<<dim3(DIM/128, BT/128),128,GEMM_SMEM>>>(Y2, Wo, out);
}

// round 17
// speedup vs baseline: 1.2299x; 1.2299x over previous
#include <cuda_runtime.h>
#include <cuda_fp16.h>
#include <math.h>

#define DIM 2048
#define NH  16
#define HD  128
#define B2  2
#define T2  2048
#define BT  4096   // B*T
#define BH  32     // B*NH

// ---------------- device scratch ----------------
__device__ __half g_Wq[DIM*DIM];
__device__ __half g_Wk[DIM*DIM];
__device__ __half g_Wv[DIM*DIM];
__device__ __half g_Wo[DIM*DIM];
__device__ __half g_Xh[BT*DIM];      // x in fp16
__device__ __half g_Qh[BH*T2*HD];    // post-RoPE fp16 (scale folded)
__device__ __half g_Kh[BH*T2*HD];
__device__ __half g_Vt[BH*HD*T2];    // V transposed fp16 [BH][HD][T]
__device__ __half g_Y2[BT*DIM];      // attention out fp16 [BT][DIM]

// ---------------- helpers ----------------
__device__ __forceinline__ void mma16(float* d, const unsigned* a, const unsigned* b){
    asm volatile("mma.sync.aligned.m16n8k16.row.col.f32.f16.f16.f32 "
                 "{%0,%1,%2,%3},{%4,%5,%6,%7},{%8,%9},{%0,%1,%2,%3};"
                 : "+f"(d[0]),"+f"(d[1]),"+f"(d[2]),"+f"(d[3])
                 : "r"(a[0]),"r"(a[1]),"r"(a[2]),"r"(a[3]),"r"(b[0]),"r"(b[1]));
}
__device__ __forceinline__ void ldsm4(unsigned* r, unsigned addr){
    asm volatile("ldmatrix.sync.aligned.m8n8.x4.shared.b16 {%0,%1,%2,%3}, [%4];"
                 : "=r"(r[0]),"=r"(r[1]),"=r"(r[2]),"=r"(r[3]) : "r"(addr));
}
__device__ __forceinline__ unsigned packh2(float a, float b){
    __half2 h = __floats2half2_rn(a, b);
    return *(unsigned*)&h;
}

// ------- dequant (4 weights) + x->fp16 convert, one launch (z slice 4) ------
__global__ void __launch_bounds__(256) prep_kernel(
    const float* __restrict__ w0, const float* __restrict__ w1,
    const float* __restrict__ w2, const float* __restrict__ w3,
    const float* __restrict__ x,
    __half* __restrict__ o0, __half* __restrict__ o1,
    __half* __restrict__ o2, __half* __restrict__ o3,
    __half* __restrict__ xo)
{
    int tid = threadIdx.x;
    if (blockIdx.y == 4){
        // convert 2 rows (4096 floats) of x per block
        size_t base = (size_t)blockIdx.x*4096 + tid*8;
        #pragma unroll
        for (int r=0;r<2;r++){
            size_t i = base + r*2048;
            float4 a = *(const float4*)(x + i);
            float4 b = *(const float4*)(x + i + 4);
            __half2 h[4];
            h[0]=__floats2half2_rn(a.x,a.y); h[1]=__floats2half2_rn(a.z,a.w);
            h[2]=__floats2half2_rn(b.x,b.y); h[3]=__floats2half2_rn(b.z,b.w);
            *(uint4*)(xo + i) = *(uint4*)h;
        }
        return;
    }
    const float* w; __half* o;
    switch (blockIdx.y){
        case 0: w=w0; o=o0; break;
        case 1: w=w1; o=o1; break;
        case 2: w=w2; o=o2; break;
        default: w=w3; o=o3; break;
    }
    int row = blockIdx.x;
    const float* wr = w + (size_t)row*DIM + tid*8;
    float v[8]; float s = 0.f;
    #pragma unroll
    for (int i=0;i<8;i++){ v[i]=wr[i]; s += fabsf(v[i]); }
    #pragma unroll
    for (int off=8; off; off>>=1)
        s += __shfl_xor_sync(0xffffffffu, s, off, 16);
    float scale = fmaxf(s*(1.0f/128.0f), 1e-8f);
    float inv = 1.0f/scale;
    __half* orow = o + (size_t)row*DIM + tid*8;
    #pragma unroll
    for (int i=0;i<4;i++){
        float wn0 = v[2*i]*inv, wn1 = v[2*i+1]*inv;
        float q0 = (wn0 > 0.5f) ? 1.0f : ((wn0 < -0.5f) ? -1.0f : 0.0f);
        float q1 = (wn1 > 0.5f) ? 1.0f : ((wn1 < -0.5f) ? -1.0f : 0.0f);
        *(__half2*)(orow + 2*i) = __floats2half2_rn(q0*scale, q1*scale);
    }
}

// ============ GEMM core: 128x128 tile, BK=64, warp 64x32 (R14 shape) =========
#define AH 72
#define GHALF (128*AH)             // halves per matrix per buffer
#define GEMM_SMEM (4*GHALF*2)      // 73728 bytes
#define SF 132                     // fp32 staging stride (words)
#define SH 130                     // fp16 staging stride (halves)

#define GEMM_MAINLOOP(A_, B_, K_) \
    int warp = tid>>5, lane = tid&31; \
    int wm   = (warp&1)<<6; \
    int wn   = (warp>>1)<<5; \
    int g    = lane>>2, t = lane&3; \
    int arow = ((lane>>3)&1)*8 + (lane&7); \
    int acol = (lane>>4)*8; \
    int brow = ((lane>>4)&1)*8 + (lane&7); \
    int bcol = ((lane>>3)&1)*8; \
    unsigned uA = (unsigned)__cvta_generic_to_shared(As); \
    unsigned uB = (unsigned)__cvta_generic_to_shared(Bs); \
    float acc[4][4][4]; \
    _Pragma("unroll") \
    for(int i=0;i<4;i++) \
        _Pragma("unroll") \
        for(int j=0;j<4;j++) \
            _Pragma("unroll") \
            for(int r=0;r<4;r++) acc[i][j][r]=0.f; \
    int lr = tid>>2; \
    int lc = (tid&3)<<4; \
    const __half* Ag = (A_) + (size_t)(bm*128 + lr)*(K_) + lc; \
    const __half* Bg = (B_) + (size_t)(bn*128 + lr)*(K_) + lc; \
    int soff[2][2]; \
    _Pragma("unroll") \
    for(int r=0;r<2;r++) \
        _Pragma("unroll") \
        for(int c=0;c<2;c++) \
            soff[r][c] = (lr + r*64)*AH + lc + c*8; \
    uint4 av[2][2], bv[2][2]; \
    _Pragma("unroll") \
    for(int r=0;r<2;r++) \
        _Pragma("unroll") \
        for(int c=0;c<2;c++){ \
            av[r][c] = *(const uint4*)(Ag + (size_t)r*64*(K_) + c*8); \
            bv[r][c] = *(const uint4*)(Bg + (size_t)r*64*(K_) + c*8); \
        } \
    _Pragma("unroll") \
    for(int r=0;r<2;r++) \
        _Pragma("unroll") \
        for(int c=0;c<2;c++){ \
            *(uint4*)&As[soff[r][c]] = av[r][c]; \
            *(uint4*)&Bs[soff[r][c]] = bv[r][c]; \
        } \
    int buf = 0; \
    for(int k0=0; k0<(K_); k0+=64){ \
        __syncthreads(); \
        bool more = (k0+64 < (K_)); \
        if (more){ \
            _Pragma("unroll") \
            for(int r=0;r<2;r++) \
                _Pragma("unroll") \
                for(int c=0;c<2;c++){ \
                    av[r][c] = *(const uint4*)(Ag + k0+64 + (size_t)r*64*(K_) + c*8); \
                    bv[r][c] = *(const uint4*)(Bg + k0+64 + (size_t)r*64*(K_) + c*8); \
                } \
        } \
        unsigned a_lane = uA + (buf*GHALF + (wm + arow)*AH + acol)*2; \
        unsigned b_lane = uB + (buf*GHALF + (wn + brow)*AH + bcol)*2; \
        _Pragma("unroll") \
        for(int ks=0;ks<4;ks++){ \
            unsigned af[4][4], bf[2][4]; \
            _Pragma("unroll") \
            for(int mi=0;mi<4;mi++) \
                ldsm4(af[mi], a_lane + (mi*16*AH + ks*16)*2); \
            _Pragma("unroll") \
            for(int p=0;p<2;p++) \
                ldsm4(bf[p], b_lane + (p*16*AH + ks*16)*2); \
            _Pragma("unroll") \
            for(int mi=0;mi<4;mi++) \
                _Pragma("unroll") \
                for(int ni=0;ni<4;ni++) \
                    mma16(acc[mi][ni], af[mi], &bf[ni>>1][(ni&1)*2]); \
        } \
        if (more){ \
            int nb = buf^1; \
            _Pragma("unroll") \
            for(int r=0;r<2;r++) \
                _Pragma("unroll") \
                for(int c=0;c<2;c++){ \
                    *(uint4*)&As[nb*GHALF + soff[r][c]] = av[r][c]; \
                    *(uint4*)&Bs[nb*GHALF + soff[r][c]] = bv[r][c]; \
                } \
        } \
        buf ^= 1; \
    }

// ---------------- fused QKV GEMM: blockIdx.z selects weight/output ----------
__global__ void __launch_bounds__(256) gemm_qkv_kernel(
    const __half* __restrict__ A,
    const __half* __restrict__ Bq, const __half* __restrict__ Bk,
    const __half* __restrict__ Bv,
    __half* __restrict__ Oq, __half* __restrict__ Ok, __half* __restrict__ Ov)
{
    extern __shared__ __align__(16) __half dsm[];
    __half* As = dsm;
    __half* Bs = dsm + 2*GHALF;
    int tid = threadIdx.x;
    int bm  = blockIdx.y, bn = blockIdx.x;
    int z   = blockIdx.z;
    const __half* Bw = (z==0) ? Bq : (z==1) ? Bk : Bv;
    __half* Ch       = (z==0) ? Oq : (z==1) ? Ok : Ov;
    float scale      = (z==0) ? 0.08838834764831845f : 1.0f;

    GEMM_MAINLOOP(A, Bw, DIM)

    __syncthreads();

    int b_ = bm >> 4;
    int tb = (bm & 15) * 128;
    int h  = bn;

    if (z < 2){
        float* S = (float*)dsm;
        #pragma unroll
        for(int mi=0;mi<4;mi++){
            #pragma unroll
            for(int ni=0;ni<4;ni++){
                int row = wm + mi*16 + g;
                int col = wn + ni*8 + 2*t;
                *(float2*)&S[row*SF + col]     = make_float2(acc[mi][ni][0], acc[mi][ni][1]);
                *(float2*)&S[(row+8)*SF + col] = make_float2(acc[mi][ni][2], acc[mi][ni][3]);
            }
        }
        __syncthreads();
        __half* outp = Ch + ((size_t)(b_*NH + h)*T2 + tb)*HD;
        #pragma unroll
        for (int k=0;k<32;k++){
            int e = tid + k*256;
            int row = e >> 6, j = e & 63;
            float x1 = S[row*SF + j], x2 = S[row*SF + j + 64];
            float invf = exp2f(-(float)j * (13.287712379549449f/64.0f));
            float ang  = (float)(tb + row) * invf;
            float sn, cs; sincosf(ang, &sn, &cs);
            outp[(size_t)row*HD + j]      = __float2half_rn((x1*cs - x2*sn)*scale);
            outp[(size_t)row*HD + j + 64] = __float2half_rn((x1*sn + x2*cs)*scale);
        }
    } else {
        __half* S = dsm;
        #pragma unroll
        for(int mi=0;mi<4;mi++){
            #pragma unroll
            for(int ni=0;ni<4;ni++){
                int row = wm + mi*16 + g;
                int col = wn + ni*8 + 2*t;
                *(__half2*)&S[row*SH + col]     = __floats2half2_rn(acc[mi][ni][0], acc[mi][ni][1]);
                *(__half2*)&S[(row+8)*SH + col] = __floats2half2_rn(acc[mi][ni][2], acc[mi][ni][3]);
            }
        }
        __syncthreads();
        __half* outp = Ch + ((size_t)(b_*NH + h)*HD)*T2 + tb;
        #pragma unroll
        for (int k=0;k<64;k++){
            int e = tid + k*256;
            int d = e >> 7, tt = e & 127;
            outp[(size_t)d*T2 + tt] = S[tt*SH + d];
        }
    }
}

// ---------------- output GEMM: fp32 row-major ----------------
__global__ void __launch_bounds__(256) gemm_out_kernel(
    const __half* __restrict__ A, const __half* __restrict__ Bw,
    float* __restrict__ Cf)
{
    extern __shared__ __align__(16) __half dsm[];
    __half* As = dsm;
    __half* Bs = dsm + 2*GHALF;
    int tid = threadIdx.x;
    int bm  = blockIdx.y, bn = blockIdx.x;

    GEMM_MAINLOOP(A, Bw, DIM)

    #pragma unroll
    for(int mi=0;mi<4;mi++){
        #pragma unroll
        for(int ni=0;ni<4;ni++){
            int rowa = bm*128 + wm + mi*16 + g;
            int col  = bn*128 + wn + ni*8 + 2*t;
            *(float2*)(Cf + (size_t)rowa*DIM + col) =
                make_float2(acc[mi][ni][0], acc[mi][ni][1]);
            *(float2*)(Cf + (size_t)(rowa+8)*DIM + col) =
                make_float2(acc[mi][ni][2], acc[mi][ni][3]);
        }
    }
}

// ---------------- fp16 flash attention: BM=64, P in registers ----------------
#define QH 136
#define VH 72
#define FL_Q (64*QH)
#define FL_K (64*QH)
#define FL_V (128*VH)
#define FL_SMEM ((FL_Q + 2*FL_K + 2*FL_V)*2)   // 89088 bytes

__global__ void __launch_bounds__(128,2) flash3_kernel(
    const __half* __restrict__ Q, const __half* __restrict__ K,
    const __half* __restrict__ Vt, __half* __restrict__ Y2)
{
    extern __shared__ __align__(16) __half smh[];
    __half* Qs = smh;                // [64][136]
    __half* Ks = Qs + FL_Q;          // 2 x [64][136]
    __half* Vs = Ks + 2*FL_K;        // 2 x [128][72]

    int qb  = (int)(gridDim.x - 1 - blockIdx.x);
    int bh  = blockIdx.y;
    int tid = threadIdx.x;
    int warp = tid >> 5, lane = tid & 31;
    int g = lane >> 2, t = lane & 3;

    int arow = ((lane>>3)&1)*8 + (lane&7);
    int acol = (lane>>4)*8;
    int brow = ((lane>>4)&1)*8 + (lane&7);
    int bcol = ((lane>>3)&1)*8;
    unsigned uQ = (unsigned)__cvta_generic_to_shared(Qs);
    unsigned uK = (unsigned)__cvta_generic_to_shared(Ks);
    unsigned uV = (unsigned)__cvta_generic_to_shared(Vs);
    unsigned q_lane = uQ + ((warp*16 + arow)*QH + acol)*2;

    const __half* qg = Q  + ((size_t)bh*T2 + qb*64)*HD;
    const __half* kg = K  + (size_t)bh*T2*HD;
    const __half* vg = Vt + (size_t)bh*HD*T2;

    int kr = tid >> 4, kc = (tid & 15) << 3;
    int vd = tid >> 3, vc = (tid & 7) << 3;

    #pragma unroll
    for (int it=0; it<8; it++){
        int idx = tid + it*128;
        int r = idx >> 4, c = (idx & 15) << 3;
        *(uint4*)&Qs[r*QH + c] = *(const uint4*)(qg + (size_t)r*HD + c);
    }
    uint4 kvreg[16];
    #pragma unroll
    for (int it=0; it<8; it++)
        kvreg[it] = *(const uint4*)(kg + (size_t)(kr + it*8)*HD + kc);
    #pragma unroll
    for (int it=0; it<8; it++)
        kvreg[8+it] = *(const uint4*)(vg + (size_t)(vd + it*16)*T2 + vc);
    #pragma unroll
    for (int it=0; it<8; it++)
        *(uint4*)&Ks[(kr + it*8)*QH + kc] = kvreg[it];
    #pragma unroll
    for (int it=0; it<8; it++)
        *(uint4*)&Vs[(vd + it*16)*VH + vc] = kvreg[8+it];

    float l0 = 0.f, l1 = 0.f;
    float o[16][4];
    #pragma unroll
    for (int i=0;i<16;i++)
        #pragma unroll
        for (int r=0;r<4;r++) o[i][r]=0.f;

    int prow = warp*16 + g;
    int nkb = qb + 1;

    for (int kb=0; kb<nkb; kb++){
        int buf = kb & 1;
        __syncthreads();
        bool more = (kb+1 < nkb);
        if (more){
            #pragma unroll
            for (int it=0; it<8; it++)
                kvreg[it] = *(const uint4*)(kg + (size_t)((kb+1)*64 + kr + it*8)*HD + kc);
            #pragma unroll
            for (int it=0; it<8; it++)
                kvreg[8+it] = *(const uint4*)(vg + (size_t)(vd + it*16)*T2 + (kb+1)*64 + vc);
        }
        unsigned k_lane = uK + (buf*FL_K + brow*QH + bcol)*2;
        unsigned v_lane = uV + (buf*FL_V + brow*VH + bcol)*2;

        float s[8][4];
        #pragma unroll
        for (int ni=0;ni<8;ni++)
            #pragma unroll
            for (int r=0;r<4;r++) s[ni][r]=0.f;
        #pragma unroll
        for (int ks=0; ks<8; ks++){
            unsigned af[4], kf[4][4];
            ldsm4(af, q_lane + ks*32);
            #pragma unroll
            for (int p=0;p<4;p++)
                ldsm4(kf[p], k_lane + (p*16*QH + ks*16)*2);
            #pragma unroll
            for (int ni=0;ni<8;ni++)
                mma16(s[ni], af, &kf[ni>>1][(ni&1)*2]);
        }

        if (kb == qb){
            int q0 = qb*64 + prow, q1 = q0 + 8;
            #pragma unroll
            for (int ni=0;ni<8;ni++){
                int k0 = kb*64 + ni*8 + 2*t;
                if (k0   > q0) s[ni][0] = -1e30f;
                if (k0+1 > q0) s[ni][1] = -1e30f;
                if (k0   > q1) s[ni][2] = -1e30f;
                if (k0+1 > q1) s[ni][3] = -1e30f;
            }
        }

        #pragma unroll
        for (int ni=0;ni<8;ni++){
            s[ni][0] = __expf(s[ni][0]); l0 += s[ni][0];
            s[ni][1] = __expf(s[ni][1]); l0 += s[ni][1];
            s[ni][2] = __expf(s[ni][2]); l1 += s[ni][2];
            s[ni][3] = __expf(s[ni][3]); l1 += s[ni][3];
        }

        #pragma unroll
        for (int ks=0; ks<4; ks++){
            unsigned af[4], vf[8][4];
            af[0] = packh2(s[2*ks][0],   s[2*ks][1]);
            af[1] = packh2(s[2*ks][2],   s[2*ks][3]);
            af[2] = packh2(s[2*ks+1][0], s[2*ks+1][1]);
            af[3] = packh2(s[2*ks+1][2], s[2*ks+1][3]);
            #pragma unroll
            for (int p=0;p<8;p++)
                ldsm4(vf[p], v_lane + (p*16*VH + ks*16)*2);
            #pragma unroll
            for (int ti=0;ti<16;ti++)
                mma16(o[ti], af, &vf[ti>>1][(ti&1)*2]);
        }

        if (more){
            int nb = buf^1;
            #pragma unroll
            for (int it=0; it<8; it++)
                *(uint4*)&Ks[nb*FL_K + (kr + it*8)*QH + kc] = kvreg[it];
            #pragma unroll
            for (int it=0; it<8; it++)
                *(uint4*)&Vs[nb*FL_V + (vd + it*16)*VH + vc] = kvreg[8+it];
        }
    }

    #pragma unroll
    for (int off=1; off<4; off<<=1){
        l0 += __shfl_xor_sync(0xffffffffu, l0, off, 4);
        l1 += __shfl_xor_sync(0xffffffffu, l1, off, 4);
    }

    float i0 = 1.0f/l0, i1 = 1.0f/l1;
    int trow = qb*64 + prow;
    int b_ = bh >> 4, h = bh & 15;
    __half* yr = Y2 + ((size_t)b_*T2)*DIM + h*HD;
    #pragma unroll
    for (int ti=0;ti<16;ti++){
        int col = ti*8 + 2*t;
        *(__half2*)(yr + (size_t)trow*DIM + col) =
            __floats2half2_rn(o[ti][0]*i0, o[ti][1]*i0);
        *(__half2*)(yr + (size_t)(trow+8)*DIM + col) =
            __floats2half2_rn(o[ti][2]*i1, o[ti][3]*i1);
    }
}

// ---------------- launch ----------------
extern "C" void kernel_launch(void* const* d_in, const int* in_sizes, int n_in,
                              void* d_out, int out_size)
{
    const float* x  = (const float*)d_in[0];
    const float* wq = (const float*)d_in[1];
    const float* wk = (const float*)d_in[2];
    const float* wv = (const float*)d_in[3];
    const float* wo = (const float*)d_in[4];
    float* out = (float*)d_out;

    __half *Wq,*Wk,*Wv,*Wo,*Xh,*Qh,*Kh,*Vt,*Y2;
    cudaGetSymbolAddress((void**)&Wq, g_Wq);
    cudaGetSymbolAddress((void**)&Wk, g_Wk);
    cudaGetSymbolAddress((void**)&Wv, g_Wv);
    cudaGetSymbolAddress((void**)&Wo, g_Wo);
    cudaGetSymbolAddress((void**)&Xh, g_Xh);
    cudaGetSymbolAddress((void**)&Qh, g_Qh);
    cudaGetSymbolAddress((void**)&Kh, g_Kh);
    cudaGetSymbolAddress((void**)&Vt, g_Vt);
    cudaGetSymbolAddress((void**)&Y2, g_Y2);

    cudaFuncSetAttribute(gemm_qkv_kernel,
        cudaFuncAttributeMaxDynamicSharedMemorySize, GEMM_SMEM);
    cudaFuncSetAttribute(gemm_out_kernel,
        cudaFuncAttributeMaxDynamicSharedMemorySize, GEMM_SMEM);
    cudaFuncSetAttribute(flash3_kernel,
        cudaFuncAttributeMaxDynamicSharedMemorySize, FL_SMEM);

    prep_kernel<<<dim3(DIM,5),256>>>(wq, wk, wv, wo, x, Wq, Wk, Wv, Wo, Xh);

    gemm_qkv_kernel<<<dim3(DIM/128, BT/128, 3),256,GEMM_SMEM>>>(
        Xh, Wq, Wk, Wv, Qh, Kh, Vt);

    flash3_kernel<<<dim3(T2/64, BH), 128, FL_SMEM>>>(Qh, Kh, Vt, Y2);

    gemm_out_kernel<<<dim3(DIM/128, BT/128),256,GEMM_SMEM>>>(Y2, Wo, out);
}